// round 8
// baseline (speedup 1.0000x reference)
#include <cuda_runtime.h>
#include <cuda_bf16.h>
#include <cstdint>
#include <cstddef>

#define N_NODES   50000
#define N_EDGES   600000
#define D         128
#define NLAYERS   5
#define N_GRAPHS  256
#define TOTAL_SUB 2560
#define BN_EPS    1e-5f
#define NTILES    391            // ceil(50000/128)

#define IMG_STRIDE_B 272
#define IMG_BYTES    34816       // 128 * 272

// ---------------- scratch (static device globals) ---------------------------
__device__ __align__(128) float g_h[N_NODES * D];      // post-BN activations
__device__ __align__(128) float g_hnew[N_NODES * D];   // pre-BN output
__device__ __align__(128) float g_agg[N_NODES * D];
__device__ __align__(16)  float g_stats[2 * D];
__device__ __align__(16)  float g_bnA[D];
__device__ __align__(16)  float g_bnB[D];
__device__                int   g_off[N_GRAPHS];
__device__ __align__(16)  float g_cnt[TOTAL_SUB];
__device__ __align__(16)  unsigned char g_Bimg[NLAYERS * 4 * IMG_BYTES];
// CSR by dst
__device__                int    g_counts[N_NODES];
__device__                int    g_rowptr[N_NODES];
__device__                int    g_cursor[N_NODES];
__device__ __align__(16)  float2 g_edges[N_EDGES];   // (src as int bits, weight)

// ---------------- helpers ----------------------------------------------------
__device__ __forceinline__ uint32_t smem_to_u32(const void* p) {
    uint32_t a;
    asm("{ .reg .u64 t; cvta.to.shared.u64 t, %1; cvt.u32.u64 %0, t; }"
        : "=r"(a) : "l"(p));
    return a;
}
__device__ __forceinline__ void red_add_v4(float* p, float4 v) {
    asm volatile("red.global.add.v4.f32 [%0], {%1,%2,%3,%4};"
                 :: "l"(p), "f"(v.x), "f"(v.y), "f"(v.z), "f"(v.w) : "memory");
}
__device__ __forceinline__ void ldsm4(uint32_t* r, uint32_t addr) {
    asm volatile("ldmatrix.sync.aligned.m8n8.x4.shared.b16 {%0,%1,%2,%3}, [%4];"
                 : "=r"(r[0]), "=r"(r[1]), "=r"(r[2]), "=r"(r[3]) : "r"(addr));
}
__device__ __forceinline__ void mma16816(float* c, const uint32_t* a,
                                         uint32_t b0, uint32_t b1) {
    asm volatile("mma.sync.aligned.m16n8k16.row.col.f32.bf16.bf16.f32 "
                 "{%0,%1,%2,%3}, {%4,%5,%6,%7}, {%8,%9}, {%0,%1,%2,%3};"
                 : "+f"(c[0]), "+f"(c[1]), "+f"(c[2]), "+f"(c[3])
                 : "r"(a[0]), "r"(a[1]), "r"(a[2]), "r"(a[3]), "r"(b0), "r"(b1));
}
__device__ __forceinline__ float4 bn_relu4(float4 v, float4 a, float4 b) {
    v.x = fmaxf(fmaf(v.x, a.x, b.x), 0.f);
    v.y = fmaxf(fmaf(v.y, a.y, b.y), 0.f);
    v.z = fmaxf(fmaf(v.z, a.z, b.z), 0.f);
    v.w = fmaxf(fmaf(v.w, a.w, b.w), 0.f);
    return v;
}

// ---------------- CSR build ---------------------------------------------------
__global__ void zero_counts_kernel() {
    int i = blockIdx.x * blockDim.x + threadIdx.x;
    if (i < N_NODES) g_counts[i] = 0;
}
__global__ void count_kernel(const int* __restrict__ dst) {
    int e = blockIdx.x * blockDim.x + threadIdx.x;
    if (e < N_EDGES) atomicAdd(&g_counts[dst[e]], 1);
}
__global__ void scan_kernel() {
    __shared__ int ssum[1024];
    int t = threadIdx.x;
    int base = t * 49;
    int s = 0;
    #pragma unroll 7
    for (int i = 0; i < 49; i++) {
        int idx = base + i;
        if (idx < N_NODES) s += g_counts[idx];
    }
    ssum[t] = s;
    __syncthreads();
    for (int off = 1; off < 1024; off <<= 1) {
        int v = (t >= off) ? ssum[t - off] : 0;
        __syncthreads();
        ssum[t] += v;
        __syncthreads();
    }
    int run = ssum[t] - s;
    for (int i = 0; i < 49; i++) {
        int idx = base + i;
        if (idx < N_NODES) {
            g_rowptr[idx] = run;
            g_cursor[idx] = run;
            run += g_counts[idx];
        }
    }
}
__global__ void fill_kernel(const int* __restrict__ src,
                            const int* __restrict__ dst,
                            const float* __restrict__ ea) {
    int e = blockIdx.x * blockDim.x + threadIdx.x;
    if (e >= N_EDGES) return;
    int d = dst[e];
    int slot = atomicAdd(&g_cursor[d], 1);
    g_edges[slot] = make_float2(__int_as_float(src[e]), ea[e]);
}

// ---------------- gather: agg[i] = sum_{j->i} w*h[j] (fp32, one warp/node) ---
__global__ void gather_kernel(const float* __restrict__ h) {
    if (blockIdx.x == 0 && threadIdx.x < (2 * D) / 4)
        ((float4*)g_stats)[threadIdx.x] = make_float4(0.f, 0.f, 0.f, 0.f);
    int t = blockIdx.x * blockDim.x + threadIdx.x;
    int node = t >> 5, lane = t & 31;
    if (node >= N_NODES) return;
    int beg = g_rowptr[node];
    int cnt = g_counts[node];
    float4 acc = {0.f, 0.f, 0.f, 0.f};
    int j = 0;
    for (; j + 2 <= cnt; j += 2) {
        float2 e0 = g_edges[beg + j];
        float2 e1 = g_edges[beg + j + 1];
        float4 v0 = ((const float4*)(h + (size_t)__float_as_int(e0.x) * D))[lane];
        float4 v1 = ((const float4*)(h + (size_t)__float_as_int(e1.x) * D))[lane];
        acc.x += e0.y * v0.x; acc.y += e0.y * v0.y;
        acc.z += e0.y * v0.z; acc.w += e0.y * v0.w;
        acc.x += e1.y * v1.x; acc.y += e1.y * v1.y;
        acc.z += e1.y * v1.z; acc.w += e1.y * v1.w;
    }
    if (j < cnt) {
        float2 e0 = g_edges[beg + j];
        float4 v0 = ((const float4*)(h + (size_t)__float_as_int(e0.x) * D))[lane];
        acc.x += e0.y * v0.x; acc.y += e0.y * v0.y;
        acc.z += e0.y * v0.z; acc.w += e0.y * v0.w;
    }
    ((float4*)(g_agg + (size_t)node * D))[lane] = acc;
}

// W[l][k][n] -> padded [n][k] bf16 hi/lo images
__global__ void prep_B_kernel(const float* __restrict__ Wrel,
                              const float* __restrict__ Wroot) {
    int idx = blockIdx.x * blockDim.x + threadIdx.x;
    if (idx >= NLAYERS * 2 * D * D) return;
    int l   = idx / (2 * D * D);
    int rem = idx % (2 * D * D);
    int mat = rem / (D * D);
    int e   = rem % (D * D);
    int n = e & 127, k = e >> 7;
    const float* W = (mat == 0) ? Wrel : Wroot;
    float x = W[(size_t)l * D * D + k * D + n];
    __nv_bfloat16 hi = __float2bfloat16_rn(x);
    float r = x - __bfloat162float(hi);
    __nv_bfloat16 lo = __float2bfloat16_rn(r);
    uint32_t off = (uint32_t)(n * IMG_STRIDE_B + k * 2);
    unsigned char* base = g_Bimg + (size_t)l * (4 * IMG_BYTES) + mat * (2 * IMG_BYTES);
    *(__nv_bfloat16*)(base + off)             = hi;
    *(__nv_bfloat16*)(base + IMG_BYTES + off) = lo;
}

// ---------------- mma.sync GEMM + fused BN stats ------------------------------
#define SM_A_HI   0
#define SM_A_LO   IMG_BYTES
#define SM_B      (2 * IMG_BYTES)
#define SM_BIAS   (6 * IMG_BYTES)
#define SM_TOTAL  (6 * IMG_BYTES + 512)

__device__ __forceinline__ void convert_rows(const float* __restrict__ src, int row0,
                                             char* sa_hi, char* sa_lo, int t) {
    int row = t >> 1, kh = (t & 1) * 64;
    bool valid = (row0 + row) < N_NODES;
    const float4* sr = (const float4*)(src + (size_t)(row0 + row) * D + kh);
    uint32_t base = (uint32_t)(row * IMG_STRIDE_B + kh * 2);
    #pragma unroll
    for (int i = 0; i < 8; i++) {
        float4 v0, v1;
        if (valid) { v0 = sr[2 * i]; v1 = sr[2 * i + 1]; }
        else       { v0 = make_float4(0.f, 0.f, 0.f, 0.f); v1 = v0; }
        float xs[8] = {v0.x, v0.y, v0.z, v0.w, v1.x, v1.y, v1.z, v1.w};
        uint32_t hp[4], lp[4];
        #pragma unroll
        for (int j = 0; j < 4; j++) {
            __nv_bfloat162 hpair = __floats2bfloat162_rn(xs[2 * j], xs[2 * j + 1]);
            float r0 = xs[2 * j]     - __low2float(hpair);
            float r1 = xs[2 * j + 1] - __high2float(hpair);
            __nv_bfloat162 lpair = __floats2bfloat162_rn(r0, r1);
            hp[j] = *(uint32_t*)&hpair;
            lp[j] = *(uint32_t*)&lpair;
        }
        *(uint4*)(sa_hi + base + i * 16) = make_uint4(hp[0], hp[1], hp[2], hp[3]);
        *(uint4*)(sa_lo + base + i * 16) = make_uint4(lp[0], lp[1], lp[2], lp[3]);
    }
}

__global__ __launch_bounds__(256, 1)
void gemm_kernel(const float* __restrict__ h,
                 const float* __restrict__ brel,
                 const float* __restrict__ broot,
                 int layer) {
    extern __shared__ char sm[];
    uint32_t smb = smem_to_u32(sm);
    const int tid = threadIdx.x;
    const int wid = tid >> 5, lane = tid & 31;
    const int wm = wid & 3, wn = wid >> 2;
    const int q = lane >> 3, lr = lane & 7;
    const int gid = lane >> 2, tg = lane & 3;

    {
        const uint4* gB = (const uint4*)(g_Bimg + (size_t)layer * (4 * IMG_BYTES));
        uint4* sB = (uint4*)(sm + SM_B);
        #pragma unroll 4
        for (int i = tid; i < (4 * IMG_BYTES) / 16; i += 256) sB[i] = gB[i];
    }
    if (tid < D) ((float*)(sm + SM_BIAS))[tid] = brel[tid] + broot[tid];
    __syncthreads();

    const uint32_t abase = (uint32_t)((wm * 32 + (q & 1) * 8 + lr) * IMG_STRIDE_B + (q >> 1) * 16);
    const uint32_t bbase = (uint32_t)((wn * 64 + (q >> 1) * 8 + lr) * IMG_STRIDE_B + (q & 1) * 16);
    const float* sbias = (const float*)(sm + SM_BIAS);

    for (int tile = blockIdx.x; tile < NTILES; tile += gridDim.x) {
        const int row0 = tile * 128;
        float acc[2][8][4];
        #pragma unroll
        for (int mt = 0; mt < 2; mt++)
            #pragma unroll
            for (int nt = 0; nt < 8; nt++)
                #pragma unroll
                for (int r = 0; r < 4; r++) acc[mt][nt][r] = 0.f;

        #pragma unroll
        for (int chunk = 0; chunk < 2; chunk++) {
            const float* src = (chunk == 0) ? g_agg : h;
            convert_rows(src, row0, sm + SM_A_HI, sm + SM_A_LO, tid);
            __syncthreads();

            const uint32_t aH = smb + SM_A_HI + abase;
            const uint32_t aL = smb + SM_A_LO + abase;
            const uint32_t bB = smb + SM_B + chunk * (2 * IMG_BYTES) + bbase;

            #pragma unroll
            for (int ks = 0; ks < 8; ks++) {
                uint32_t ah0[4], ah1[4], al0[4], al1[4];
                ldsm4(ah0, aH + ks * 32);
                ldsm4(ah1, aH + 16 * IMG_STRIDE_B + ks * 32);
                ldsm4(al0, aL + ks * 32);
                ldsm4(al1, aL + 16 * IMG_STRIDE_B + ks * 32);
                uint32_t bh[4][4], bl[4][4];
                #pragma unroll
                for (int nt2 = 0; nt2 < 4; nt2++) {
                    ldsm4(bh[nt2], bB + nt2 * 16 * IMG_STRIDE_B + ks * 32);
                    ldsm4(bl[nt2], bB + IMG_BYTES + nt2 * 16 * IMG_STRIDE_B + ks * 32);
                }
                #pragma unroll
                for (int nt = 0; nt < 8; nt++) {
                    uint32_t b0h = bh[nt >> 1][(nt & 1) * 2];
                    uint32_t b1h = bh[nt >> 1][(nt & 1) * 2 + 1];
                    uint32_t b0l = bl[nt >> 1][(nt & 1) * 2];
                    uint32_t b1l = bl[nt >> 1][(nt & 1) * 2 + 1];
                    mma16816(acc[0][nt], ah0, b0h, b1h);
                    mma16816(acc[1][nt], ah1, b0h, b1h);
                    mma16816(acc[0][nt], al0, b0h, b1h);
                    mma16816(acc[1][nt], al1, b0h, b1h);
                    mma16816(acc[0][nt], ah0, b0l, b1l);
                    mma16816(acc[1][nt], ah1, b0l, b1l);
                }
            }
            __syncthreads();
        }

        // epilogue: bias + store + fused BN partial stats
        #pragma unroll
        for (int nt = 0; nt < 8; nt++) {
            int c = wn * 64 + nt * 8 + tg * 2;
            float bx = sbias[c], by = sbias[c + 1];
            float s0 = 0.f, s1 = 0.f, q0 = 0.f, q1 = 0.f;
            #pragma unroll
            for (int mt = 0; mt < 2; mt++) {
                int r0 = row0 + wm * 32 + mt * 16 + gid;
                if (r0 < N_NODES) {
                    float ox = acc[mt][nt][0] + bx, oy = acc[mt][nt][1] + by;
                    *(float2*)(g_hnew + (size_t)r0 * D + c) = make_float2(ox, oy);
                    s0 += ox; s1 += oy; q0 += ox * ox; q1 += oy * oy;
                }
                if (r0 + 8 < N_NODES) {
                    float ox = acc[mt][nt][2] + bx, oy = acc[mt][nt][3] + by;
                    *(float2*)(g_hnew + (size_t)(r0 + 8) * D + c) = make_float2(ox, oy);
                    s0 += ox; s1 += oy; q0 += ox * ox; q1 += oy * oy;
                }
            }
            #pragma unroll
            for (int off = 16; off >= 4; off >>= 1) {
                s0 += __shfl_down_sync(0xffffffffu, s0, off);
                s1 += __shfl_down_sync(0xffffffffu, s1, off);
                q0 += __shfl_down_sync(0xffffffffu, q0, off);
                q1 += __shfl_down_sync(0xffffffffu, q1, off);
            }
            if (lane < 4) {
                atomicAdd(&g_stats[c],         s0);
                atomicAdd(&g_stats[c + 1],     s1);
                atomicAdd(&g_stats[D + c],     q0);
                atomicAdd(&g_stats[D + c + 1], q1);
            }
        }
        __syncthreads();
    }
}

// ---------------- fused BN-finalize + normalize + relu ------------------------
__global__ void norm_relu_kernel(const float* __restrict__ gamma,
                                 const float* __restrict__ beta) {
    __shared__ float sA[D], sB[D];
    int t = threadIdx.x;
    if (t < D) {
        float mu  = g_stats[t] * (1.0f / N_NODES);
        float var = g_stats[D + t] * (1.0f / N_NODES) - mu * mu;
        float inv = rsqrtf(var + BN_EPS);
        float a   = gamma[t] * inv;
        sA[t] = a;
        sB[t] = beta[t] - mu * a;
    }
    __syncthreads();
    int i = blockIdx.x * blockDim.x + t;
    if (i >= N_NODES * (D / 4)) return;
    int cg = i & 31;
    float4 a = ((const float4*)sA)[cg];
    float4 b = ((const float4*)sB)[cg];
    float4 v = ((const float4*)g_hnew)[i];
    ((float4*)g_h)[i] = bn_relu4(v, a, b);
}

// last layer: just compute coefficients; pool applies them
__global__ void bn_finalize_kernel(const float* __restrict__ gamma,
                                   const float* __restrict__ beta) {
    int c = threadIdx.x;
    float mu  = g_stats[c] * (1.0f / N_NODES);
    float var = g_stats[D + c] * (1.0f / N_NODES) - mu * mu;
    float inv = rsqrtf(var + BN_EPS);
    float a   = gamma[c] * inv;
    g_bnA[c] = a;
    g_bnB[c] = beta[c] - mu * a;
}

// ---------------- pooling ----------------------------------------------------
__global__ void offsets_kernel(const int* __restrict__ nsub) {
    if (blockIdx.x == 0 && threadIdx.x == 0) {
        int acc = 0;
        for (int g = 0; g < N_GRAPHS; g++) { g_off[g] = acc; acc += nsub[g]; }
    }
}
__global__ void zero_out_kernel(float* __restrict__ out) {
    int i = blockIdx.x * blockDim.x + threadIdx.x;
    float4 z = {0.f, 0.f, 0.f, 0.f};
    if (i < TOTAL_SUB * (D / 4)) ((float4*)out)[i] = z;
    if (i < TOTAL_SUB / 4) ((float4*)g_cnt)[i] = z;
}
// pool reads final hnew (pre-BN), applies last layer's BN+relu on the fly
__global__ void pool_kernel(const int* __restrict__ batch,
                            const int* __restrict__ subb,
                            float* __restrict__ out) {
    int t = blockIdx.x * blockDim.x + threadIdx.x;
    int node = t >> 5, lane = t & 31;
    if (node >= N_NODES) return;
    float4 a4 = ((const float4*)g_bnA)[lane];
    float4 b4 = ((const float4*)g_bnB)[lane];
    int sid = g_off[batch[node]] + subb[node];
    float4 v = ((const float4*)(g_hnew + (size_t)node * D))[lane];
    v = bn_relu4(v, a4, b4);
    red_add_v4(out + (size_t)sid * D + lane * 4, v);
    if (lane == 0) atomicAdd(g_cnt + sid, 1.f);
}
__global__ void div_kernel(float* __restrict__ out) {
    int i = blockIdx.x * blockDim.x + threadIdx.x;
    if (i >= TOTAL_SUB * (D / 4)) return;
    float inv = 1.0f / fmaxf(g_cnt[i >> 5], 1.0f);
    float4 v = ((float4*)out)[i];
    v.x *= inv; v.y *= inv; v.z *= inv; v.w *= inv;
    ((float4*)out)[i] = v;
}

// ---------------- launch ------------------------------------------------------
extern "C" void kernel_launch(void* const* d_in, const int* in_sizes, int n_in,
                              void* d_out, int out_size) {
    const float* x     = (const float*)d_in[0];
    const float* ea    = (const float*)d_in[1];
    const float* Wrel  = (const float*)d_in[2];
    const float* brel  = (const float*)d_in[3];
    const float* Wroot = (const float*)d_in[4];
    const float* broot = (const float*)d_in[5];
    const float* gamma = (const float*)d_in[6];
    const float* beta  = (const float*)d_in[7];
    const int*   ei    = (const int*)d_in[8];
    const int*   batch = (const int*)d_in[9];
    const int*   nsub  = (const int*)d_in[10];
    const int*   subb  = (const int*)d_in[11];
    float*       out   = (float*)d_out;

    cudaFuncSetAttribute(gemm_kernel,
                         cudaFuncAttributeMaxDynamicSharedMemorySize, SM_TOTAL);

    void* p = nullptr;
    cudaGetSymbolAddress(&p, g_h);
    const float* gh = (const float*)p;

    const int* src = ei;
    const int* dst = ei + N_EDGES;

    zero_counts_kernel<<<(N_NODES + 255) / 256, 256>>>();                     // 1
    count_kernel<<<(N_EDGES + 255) / 256, 256>>>(dst);                        // 2
    scan_kernel<<<1, 1024>>>();                                               // 3
    fill_kernel<<<(N_EDGES + 255) / 256, 256>>>(src, dst, ea);                // 4
    offsets_kernel<<<1, 32>>>(nsub);                                          // 5

    const float* hcur = x;
    for (int l = 0; l < NLAYERS; l++) {
        gather_kernel<<<(N_NODES * 32 + 255) / 256, 256>>>(hcur);             // 6 <- ncu
        if (l == 0)
            prep_B_kernel<<<(NLAYERS * 2 * D * D + 255) / 256, 256>>>(Wrel, Wroot);
        gemm_kernel<<<148, 256, SM_TOTAL>>>(hcur,
                                            brel + (size_t)l * D,
                                            broot + (size_t)l * D, l);
        if (l < NLAYERS - 1) {
            norm_relu_kernel<<<(N_NODES * (D / 4) + 255) / 256, 256>>>(
                gamma + (size_t)l * D, beta + (size_t)l * D);
            hcur = gh;
        } else {
            bn_finalize_kernel<<<1, D>>>(gamma + (size_t)l * D,
                                         beta + (size_t)l * D);
        }
    }
    zero_out_kernel<<<(TOTAL_SUB * (D / 4) + 255) / 256, 256>>>(out);
    pool_kernel<<<(N_NODES * 32 + 255) / 256, 256>>>(batch, subb, out);
    div_kernel<<<(TOTAL_SUB * (D / 4) + 255) / 256, 256>>>(out);
}

// round 9
// speedup vs baseline: 1.1464x; 1.1464x over previous
#include <cuda_runtime.h>
#include <cuda_bf16.h>
#include <cstdint>
#include <cstddef>

#define N_NODES   50000
#define N_EDGES   600000
#define D         128
#define NLAYERS   5
#define N_GRAPHS  256
#define TOTAL_SUB 2560
#define BN_EPS    1e-5f
#define NTILES    391            // ceil(50000/128)

#define IMG_STRIDE_B 272
#define IMG_BYTES    34816       // 128 * 272

// ---------------- scratch (static device globals) ---------------------------
__device__ __align__(128) float g_h[N_NODES * D];      // post-BN activations
__device__ __align__(128) float g_hnew[N_NODES * D];   // pre-BN output
__device__ __align__(128) float g_agg[N_NODES * D];
__device__ __align__(16)  float g_stats[2 * D];
__device__ __align__(16)  float g_bnA[D];
__device__ __align__(16)  float g_bnB[D];
__device__                int   g_off[N_GRAPHS];
__device__ __align__(16)  float g_cnt[TOTAL_SUB];
__device__ __align__(16)  unsigned char g_Bimg[NLAYERS * 4 * IMG_BYTES];
// CSR by dst
__device__                int    g_counts[N_NODES];
__device__                int    g_rowptr[N_NODES];
__device__                int    g_cursor[N_NODES];
__device__ __align__(16)  float2 g_edges[N_EDGES];   // (src as int bits, weight)

// ---------------- helpers ----------------------------------------------------
__device__ __forceinline__ uint32_t smem_to_u32(const void* p) {
    uint32_t a;
    asm("{ .reg .u64 t; cvta.to.shared.u64 t, %1; cvt.u32.u64 %0, t; }"
        : "=r"(a) : "l"(p));
    return a;
}
__device__ __forceinline__ void red_add_v4(float* p, float4 v) {
    asm volatile("red.global.add.v4.f32 [%0], {%1,%2,%3,%4};"
                 :: "l"(p), "f"(v.x), "f"(v.y), "f"(v.z), "f"(v.w) : "memory");
}
__device__ __forceinline__ void ldsm4(uint32_t* r, uint32_t addr) {
    asm volatile("ldmatrix.sync.aligned.m8n8.x4.shared.b16 {%0,%1,%2,%3}, [%4];"
                 : "=r"(r[0]), "=r"(r[1]), "=r"(r[2]), "=r"(r[3]) : "r"(addr));
}
__device__ __forceinline__ void mma16816(float* c, const uint32_t* a,
                                         uint32_t b0, uint32_t b1) {
    asm volatile("mma.sync.aligned.m16n8k16.row.col.f32.bf16.bf16.f32 "
                 "{%0,%1,%2,%3}, {%4,%5,%6,%7}, {%8,%9}, {%0,%1,%2,%3};"
                 : "+f"(c[0]), "+f"(c[1]), "+f"(c[2]), "+f"(c[3])
                 : "r"(a[0]), "r"(a[1]), "r"(a[2]), "r"(a[3]), "r"(b0), "r"(b1));
}
__device__ __forceinline__ float4 bn_relu4(float4 v, float4 a, float4 b) {
    v.x = fmaxf(fmaf(v.x, a.x, b.x), 0.f);
    v.y = fmaxf(fmaf(v.y, a.y, b.y), 0.f);
    v.z = fmaxf(fmaf(v.z, a.z, b.z), 0.f);
    v.w = fmaxf(fmaf(v.w, a.w, b.w), 0.f);
    return v;
}

// ---------------- CSR build ---------------------------------------------------
__global__ void zero_counts_kernel() {
    int i = blockIdx.x * blockDim.x + threadIdx.x;
    if (i < N_NODES) g_counts[i] = 0;
}
__global__ void count_kernel(const int* __restrict__ dst) {
    int e = blockIdx.x * blockDim.x + threadIdx.x;
    if (e < N_EDGES) atomicAdd(&g_counts[dst[e]], 1);
}
__global__ void scan_kernel() {
    __shared__ int ssum[1024];
    int t = threadIdx.x;
    int base = t * 49;
    int s = 0;
    #pragma unroll 7
    for (int i = 0; i < 49; i++) {
        int idx = base + i;
        if (idx < N_NODES) s += g_counts[idx];
    }
    ssum[t] = s;
    __syncthreads();
    for (int off = 1; off < 1024; off <<= 1) {
        int v = (t >= off) ? ssum[t - off] : 0;
        __syncthreads();
        ssum[t] += v;
        __syncthreads();
    }
    int run = ssum[t] - s;
    for (int i = 0; i < 49; i++) {
        int idx = base + i;
        if (idx < N_NODES) {
            g_rowptr[idx] = run;
            g_cursor[idx] = run;
            run += g_counts[idx];
        }
    }
}
__global__ void fill_kernel(const int* __restrict__ src,
                            const int* __restrict__ dst,
                            const float* __restrict__ ea) {
    int e = blockIdx.x * blockDim.x + threadIdx.x;
    if (e >= N_EDGES) return;
    int d = dst[e];
    int slot = atomicAdd(&g_cursor[d], 1);
    g_edges[slot] = make_float2(__int_as_float(src[e]), ea[e]);
}

// ---------------- gather: agg[i] = sum_{j->i} w*h[j] (fp32, 1 warp/node) -----
__global__ void gather_kernel(const float* __restrict__ h) {
    if (blockIdx.x == 0 && threadIdx.x < (2 * D) / 4)
        ((float4*)g_stats)[threadIdx.x] = make_float4(0.f, 0.f, 0.f, 0.f);
    int t = blockIdx.x * blockDim.x + threadIdx.x;
    int node = t >> 5, lane = t & 31;
    if (node >= N_NODES) return;
    int beg = g_rowptr[node];
    int cnt = g_counts[node];
    float4 acc = {0.f, 0.f, 0.f, 0.f};
    int j = 0;
    for (; j + 4 <= cnt; j += 4) {
        float2 e0 = g_edges[beg + j];
        float2 e1 = g_edges[beg + j + 1];
        float2 e2 = g_edges[beg + j + 2];
        float2 e3 = g_edges[beg + j + 3];
        float4 v0 = ((const float4*)(h + (size_t)__float_as_int(e0.x) * D))[lane];
        float4 v1 = ((const float4*)(h + (size_t)__float_as_int(e1.x) * D))[lane];
        float4 v2 = ((const float4*)(h + (size_t)__float_as_int(e2.x) * D))[lane];
        float4 v3 = ((const float4*)(h + (size_t)__float_as_int(e3.x) * D))[lane];
        acc.x += e0.y * v0.x; acc.y += e0.y * v0.y; acc.z += e0.y * v0.z; acc.w += e0.y * v0.w;
        acc.x += e1.y * v1.x; acc.y += e1.y * v1.y; acc.z += e1.y * v1.z; acc.w += e1.y * v1.w;
        acc.x += e2.y * v2.x; acc.y += e2.y * v2.y; acc.z += e2.y * v2.z; acc.w += e2.y * v2.w;
        acc.x += e3.y * v3.x; acc.y += e3.y * v3.y; acc.z += e3.y * v3.z; acc.w += e3.y * v3.w;
    }
    for (; j < cnt; j++) {
        float2 e0 = g_edges[beg + j];
        float4 v0 = ((const float4*)(h + (size_t)__float_as_int(e0.x) * D))[lane];
        acc.x += e0.y * v0.x; acc.y += e0.y * v0.y;
        acc.z += e0.y * v0.z; acc.w += e0.y * v0.w;
    }
    ((float4*)(g_agg + (size_t)node * D))[lane] = acc;
}

// W[l][k][n] -> padded [n][k] bf16 hi/lo images
__global__ void prep_B_kernel(const float* __restrict__ Wrel,
                              const float* __restrict__ Wroot) {
    int idx = blockIdx.x * blockDim.x + threadIdx.x;
    if (idx >= NLAYERS * 2 * D * D) return;
    int l   = idx / (2 * D * D);
    int rem = idx % (2 * D * D);
    int mat = rem / (D * D);
    int e   = rem % (D * D);
    int n = e & 127, k = e >> 7;
    const float* W = (mat == 0) ? Wrel : Wroot;
    float x = W[(size_t)l * D * D + k * D + n];
    __nv_bfloat16 hi = __float2bfloat16_rn(x);
    float r = x - __bfloat162float(hi);
    __nv_bfloat16 lo = __float2bfloat16_rn(r);
    uint32_t off = (uint32_t)(n * IMG_STRIDE_B + k * 2);
    unsigned char* base = g_Bimg + (size_t)l * (4 * IMG_BYTES) + mat * (2 * IMG_BYTES);
    *(__nv_bfloat16*)(base + off)             = hi;
    *(__nv_bfloat16*)(base + IMG_BYTES + off) = lo;
}

// ---------------- mma.sync GEMM (R4 plain epilogue) ---------------------------
#define SM_A_HI   0
#define SM_A_LO   IMG_BYTES
#define SM_B      (2 * IMG_BYTES)
#define SM_BIAS   (6 * IMG_BYTES)
#define SM_TOTAL  (6 * IMG_BYTES + 512)

__device__ __forceinline__ void convert_rows(const float* __restrict__ src, int row0,
                                             char* sa_hi, char* sa_lo, int t) {
    int row = t >> 1, kh = (t & 1) * 64;
    bool valid = (row0 + row) < N_NODES;
    const float4* sr = (const float4*)(src + (size_t)(row0 + row) * D + kh);
    uint32_t base = (uint32_t)(row * IMG_STRIDE_B + kh * 2);
    #pragma unroll
    for (int i = 0; i < 8; i++) {
        float4 v0, v1;
        if (valid) { v0 = sr[2 * i]; v1 = sr[2 * i + 1]; }
        else       { v0 = make_float4(0.f, 0.f, 0.f, 0.f); v1 = v0; }
        float xs[8] = {v0.x, v0.y, v0.z, v0.w, v1.x, v1.y, v1.z, v1.w};
        uint32_t hp[4], lp[4];
        #pragma unroll
        for (int j = 0; j < 4; j++) {
            __nv_bfloat162 hpair = __floats2bfloat162_rn(xs[2 * j], xs[2 * j + 1]);
            float r0 = xs[2 * j]     - __low2float(hpair);
            float r1 = xs[2 * j + 1] - __high2float(hpair);
            __nv_bfloat162 lpair = __floats2bfloat162_rn(r0, r1);
            hp[j] = *(uint32_t*)&hpair;
            lp[j] = *(uint32_t*)&lpair;
        }
        *(uint4*)(sa_hi + base + i * 16) = make_uint4(hp[0], hp[1], hp[2], hp[3]);
        *(uint4*)(sa_lo + base + i * 16) = make_uint4(lp[0], lp[1], lp[2], lp[3]);
    }
}

__global__ __launch_bounds__(256, 1)
void gemm_kernel(const float* __restrict__ h,
                 const float* __restrict__ brel,
                 const float* __restrict__ broot,
                 int layer) {
    extern __shared__ char sm[];
    uint32_t smb = smem_to_u32(sm);
    const int tid = threadIdx.x;
    const int wid = tid >> 5, lane = tid & 31;
    const int wm = wid & 3, wn = wid >> 2;
    const int q = lane >> 3, lr = lane & 7;
    const int gid = lane >> 2, tg = lane & 3;

    {
        const uint4* gB = (const uint4*)(g_Bimg + (size_t)layer * (4 * IMG_BYTES));
        uint4* sB = (uint4*)(sm + SM_B);
        #pragma unroll 4
        for (int i = tid; i < (4 * IMG_BYTES) / 16; i += 256) sB[i] = gB[i];
    }
    if (tid < D) ((float*)(sm + SM_BIAS))[tid] = brel[tid] + broot[tid];
    __syncthreads();

    const uint32_t abase = (uint32_t)((wm * 32 + (q & 1) * 8 + lr) * IMG_STRIDE_B + (q >> 1) * 16);
    const uint32_t bbase = (uint32_t)((wn * 64 + (q >> 1) * 8 + lr) * IMG_STRIDE_B + (q & 1) * 16);
    const float* sbias = (const float*)(sm + SM_BIAS);

    for (int tile = blockIdx.x; tile < NTILES; tile += gridDim.x) {
        const int row0 = tile * 128;
        float acc[2][8][4];
        #pragma unroll
        for (int mt = 0; mt < 2; mt++)
            #pragma unroll
            for (int nt = 0; nt < 8; nt++)
                #pragma unroll
                for (int r = 0; r < 4; r++) acc[mt][nt][r] = 0.f;

        #pragma unroll
        for (int chunk = 0; chunk < 2; chunk++) {
            const float* src = (chunk == 0) ? g_agg : h;
            convert_rows(src, row0, sm + SM_A_HI, sm + SM_A_LO, tid);
            __syncthreads();

            const uint32_t aH = smb + SM_A_HI + abase;
            const uint32_t aL = smb + SM_A_LO + abase;
            const uint32_t bB = smb + SM_B + chunk * (2 * IMG_BYTES) + bbase;

            #pragma unroll
            for (int ks = 0; ks < 8; ks++) {
                uint32_t ah0[4], ah1[4], al0[4], al1[4];
                ldsm4(ah0, aH + ks * 32);
                ldsm4(ah1, aH + 16 * IMG_STRIDE_B + ks * 32);
                ldsm4(al0, aL + ks * 32);
                ldsm4(al1, aL + 16 * IMG_STRIDE_B + ks * 32);
                uint32_t bh[4][4], bl[4][4];
                #pragma unroll
                for (int nt2 = 0; nt2 < 4; nt2++) {
                    ldsm4(bh[nt2], bB + nt2 * 16 * IMG_STRIDE_B + ks * 32);
                    ldsm4(bl[nt2], bB + IMG_BYTES + nt2 * 16 * IMG_STRIDE_B + ks * 32);
                }
                #pragma unroll
                for (int nt = 0; nt < 8; nt++) {
                    uint32_t b0h = bh[nt >> 1][(nt & 1) * 2];
                    uint32_t b1h = bh[nt >> 1][(nt & 1) * 2 + 1];
                    uint32_t b0l = bl[nt >> 1][(nt & 1) * 2];
                    uint32_t b1l = bl[nt >> 1][(nt & 1) * 2 + 1];
                    mma16816(acc[0][nt], ah0, b0h, b1h);
                    mma16816(acc[1][nt], ah1, b0h, b1h);
                    mma16816(acc[0][nt], al0, b0h, b1h);
                    mma16816(acc[1][nt], al1, b0h, b1h);
                    mma16816(acc[0][nt], ah0, b0l, b1l);
                    mma16816(acc[1][nt], ah1, b0l, b1l);
                }
            }
            __syncthreads();
        }

        #pragma unroll
        for (int mt = 0; mt < 2; mt++) {
            int r0 = row0 + wm * 32 + mt * 16 + gid;
            #pragma unroll
            for (int nt = 0; nt < 8; nt++) {
                int c = wn * 64 + nt * 8 + tg * 2;
                float bx = sbias[c], by = sbias[c + 1];
                if (r0 < N_NODES) {
                    float2 o = {acc[mt][nt][0] + bx, acc[mt][nt][1] + by};
                    *(float2*)(g_hnew + (size_t)r0 * D + c) = o;
                }
                if (r0 + 8 < N_NODES) {
                    float2 o = {acc[mt][nt][2] + bx, acc[mt][nt][3] + by};
                    *(float2*)(g_hnew + (size_t)(r0 + 8) * D + c) = o;
                }
            }
        }
        __syncthreads();
    }
}

// ---------------- BN stats over hnew -----------------------------------------
__global__ void stats_kernel() {
    __shared__ float red[256 * 8];
    int t = threadIdx.x;
    float4 ps = {0.f,0.f,0.f,0.f}, pq = {0.f,0.f,0.f,0.f};
    const float4* src = (const float4*)g_hnew;
    for (int i = blockIdx.x * blockDim.x + t; i < N_NODES * (D / 4);
         i += gridDim.x * blockDim.x) {
        float4 v = src[i];
        ps.x += v.x; ps.y += v.y; ps.z += v.z; ps.w += v.w;
        pq.x += v.x*v.x; pq.y += v.y*v.y; pq.z += v.z*v.z; pq.w += v.w*v.w;
    }
    red[t*8+0]=ps.x; red[t*8+1]=ps.y; red[t*8+2]=ps.z; red[t*8+3]=ps.w;
    red[t*8+4]=pq.x; red[t*8+5]=pq.y; red[t*8+6]=pq.z; red[t*8+7]=pq.w;
    __syncthreads();
    if (t < D) {
        float s = 0.f, q = 0.f;
        #pragma unroll
        for (int g2 = 0; g2 < 8; g2++) {
            int st = g2 * 32 + (t >> 2);
            s += red[st * 8 + (t & 3)];
            q += red[st * 8 + 4 + (t & 3)];
        }
        atomicAdd(g_stats + t, s);
        atomicAdd(g_stats + D + t, q);
    }
}

// ---------------- fused BN-finalize + normalize + relu (layers 0..3) ----------
__global__ void norm_relu_kernel(const float* __restrict__ gamma,
                                 const float* __restrict__ beta) {
    __shared__ float sA[D], sB[D];
    int t = threadIdx.x;
    if (t < D) {
        float mu  = g_stats[t] * (1.0f / N_NODES);
        float var = g_stats[D + t] * (1.0f / N_NODES) - mu * mu;
        float inv = rsqrtf(var + BN_EPS);
        float a   = gamma[t] * inv;
        sA[t] = a;
        sB[t] = beta[t] - mu * a;
    }
    __syncthreads();
    int i = blockIdx.x * blockDim.x + t;
    if (i >= N_NODES * (D / 4)) return;
    int cg = i & 31;
    float4 a = ((const float4*)sA)[cg];
    float4 b = ((const float4*)sB)[cg];
    float4 v = ((const float4*)g_hnew)[i];
    ((float4*)g_h)[i] = bn_relu4(v, a, b);
}

// last layer: just compute coefficients; pool applies them
__global__ void bn_finalize_kernel(const float* __restrict__ gamma,
                                   const float* __restrict__ beta) {
    int c = threadIdx.x;
    float mu  = g_stats[c] * (1.0f / N_NODES);
    float var = g_stats[D + c] * (1.0f / N_NODES) - mu * mu;
    float inv = rsqrtf(var + BN_EPS);
    float a   = gamma[c] * inv;
    g_bnA[c] = a;
    g_bnB[c] = beta[c] - mu * a;
}

// ---------------- pooling ----------------------------------------------------
__global__ void offsets_kernel(const int* __restrict__ nsub) {
    if (blockIdx.x == 0 && threadIdx.x == 0) {
        int acc = 0;
        for (int g = 0; g < N_GRAPHS; g++) { g_off[g] = acc; acc += nsub[g]; }
    }
}
__global__ void zero_out_kernel(float* __restrict__ out) {
    int i = blockIdx.x * blockDim.x + threadIdx.x;
    float4 z = {0.f, 0.f, 0.f, 0.f};
    if (i < TOTAL_SUB * (D / 4)) ((float4*)out)[i] = z;
    if (i < TOTAL_SUB / 4) ((float4*)g_cnt)[i] = z;
}
// pool reads final hnew (pre-BN), applies last layer's BN+relu on the fly
__global__ void pool_kernel(const int* __restrict__ batch,
                            const int* __restrict__ subb,
                            float* __restrict__ out) {
    int t = blockIdx.x * blockDim.x + threadIdx.x;
    int node = t >> 5, lane = t & 31;
    if (node >= N_NODES) return;
    float4 a4 = ((const float4*)g_bnA)[lane];
    float4 b4 = ((const float4*)g_bnB)[lane];
    int sid = g_off[batch[node]] + subb[node];
    float4 v = ((const float4*)(g_hnew + (size_t)node * D))[lane];
    v = bn_relu4(v, a4, b4);
    red_add_v4(out + (size_t)sid * D + lane * 4, v);
    if (lane == 0) atomicAdd(g_cnt + sid, 1.f);
}
__global__ void div_kernel(float* __restrict__ out) {
    int i = blockIdx.x * blockDim.x + threadIdx.x;
    if (i >= TOTAL_SUB * (D / 4)) return;
    float inv = 1.0f / fmaxf(g_cnt[i >> 5], 1.0f);
    float4 v = ((float4*)out)[i];
    v.x *= inv; v.y *= inv; v.z *= inv; v.w *= inv;
    ((float4*)out)[i] = v;
}

// ---------------- launch ------------------------------------------------------
extern "C" void kernel_launch(void* const* d_in, const int* in_sizes, int n_in,
                              void* d_out, int out_size) {
    const float* x     = (const float*)d_in[0];
    const float* ea    = (const float*)d_in[1];
    const float* Wrel  = (const float*)d_in[2];
    const float* brel  = (const float*)d_in[3];
    const float* Wroot = (const float*)d_in[4];
    const float* broot = (const float*)d_in[5];
    const float* gamma = (const float*)d_in[6];
    const float* beta  = (const float*)d_in[7];
    const int*   ei    = (const int*)d_in[8];
    const int*   batch = (const int*)d_in[9];
    const int*   nsub  = (const int*)d_in[10];
    const int*   subb  = (const int*)d_in[11];
    float*       out   = (float*)d_out;

    cudaFuncSetAttribute(gemm_kernel,
                         cudaFuncAttributeMaxDynamicSharedMemorySize, SM_TOTAL);

    void* p = nullptr;
    cudaGetSymbolAddress(&p, g_h);
    const float* gh = (const float*)p;

    const int* src = ei;
    const int* dst = ei + N_EDGES;

    zero_counts_kernel<<<(N_NODES + 255) / 256, 256>>>();                     // 1
    count_kernel<<<(N_EDGES + 255) / 256, 256>>>(dst);                        // 2
    scan_kernel<<<1, 1024>>>();                                               // 3
    fill_kernel<<<(N_EDGES + 255) / 256, 256>>>(src, dst, ea);                // 4
    offsets_kernel<<<1, 32>>>(nsub);                                          // 5

    const float* hcur = x;
    for (int l = 0; l < NLAYERS; l++) {
        gather_kernel<<<(N_NODES * 32 + 255) / 256, 256>>>(hcur);             // 6 <- ncu
        if (l == 0)
            prep_B_kernel<<<(NLAYERS * 2 * D * D + 255) / 256, 256>>>(Wrel, Wroot);
        gemm_kernel<<<148, 256, SM_TOTAL>>>(hcur,
                                            brel + (size_t)l * D,
                                            broot + (size_t)l * D, l);
        stats_kernel<<<592, 256>>>();
        if (l < NLAYERS - 1) {
            norm_relu_kernel<<<(N_NODES * (D / 4) + 255) / 256, 256>>>(
                gamma + (size_t)l * D, beta + (size_t)l * D);
            hcur = gh;
        } else {
            bn_finalize_kernel<<<1, D>>>(gamma + (size_t)l * D,
                                         beta + (size_t)l * D);
        }
    }
    zero_out_kernel<<<(TOTAL_SUB * (D / 4) + 255) / 256, 256>>>(out);
    pool_kernel<<<(N_NODES * 32 + 255) / 256, 256>>>(batch, subb, out);
    div_kernel<<<(TOTAL_SUB * (D / 4) + 255) / 256, 256>>>(out);
}

// round 11
// speedup vs baseline: 1.1617x; 1.0133x over previous
#include <cuda_runtime.h>
#include <cuda_bf16.h>
#include <cstdint>
#include <cstddef>

#define N_NODES   50000
#define N_EDGES   600000
#define D         128
#define NLAYERS   5
#define N_GRAPHS  256
#define TOTAL_SUB 2560
#define BN_EPS    1e-5f
#define NTILES    391            // ceil(50000/128)

#define IMG_STRIDE_B 272
#define IMG_BYTES    34816       // 128 * 272

// ---------------- scratch (static device globals) ---------------------------
__device__ __align__(128) float g_h[N_NODES * D];      // post-BN activations
__device__ __align__(128) float g_hnew[N_NODES * D];   // pre-BN output
__device__ __align__(128) float g_agg[N_NODES * D];
__device__ __align__(16)  float g_stats[2 * D];
__device__ __align__(16)  float g_bnA[D];
__device__ __align__(16)  float g_bnB[D];
__device__                int   g_off[N_GRAPHS];
__device__ __align__(16)  float g_cnt[TOTAL_SUB];
__device__ __align__(16)  unsigned char g_Bimg[NLAYERS * 4 * IMG_BYTES];
// CSR by dst
__device__                int    g_counts[N_NODES];
__device__                int    g_rowptr[N_NODES];
__device__                int    g_cursor[N_NODES];
__device__ __align__(16)  float2 g_edges[N_EDGES];   // (src as int bits, weight)

// ---------------- helpers ----------------------------------------------------
__device__ __forceinline__ uint32_t smem_to_u32(const void* p) {
    uint32_t a;
    asm("{ .reg .u64 t; cvta.to.shared.u64 t, %1; cvt.u32.u64 %0, t; }"
        : "=r"(a) : "l"(p));
    return a;
}
__device__ __forceinline__ void red_add_v4(float* p, float4 v) {
    asm volatile("red.global.add.v4.f32 [%0], {%1,%2,%3,%4};"
                 :: "l"(p), "f"(v.x), "f"(v.y), "f"(v.z), "f"(v.w) : "memory");
}
__device__ __forceinline__ void ldsm4(uint32_t* r, uint32_t addr) {
    asm volatile("ldmatrix.sync.aligned.m8n8.x4.shared.b16 {%0,%1,%2,%3}, [%4];"
                 : "=r"(r[0]), "=r"(r[1]), "=r"(r[2]), "=r"(r[3]) : "r"(addr));
}
__device__ __forceinline__ void mma16816(float* c, const uint32_t* a,
                                         uint32_t b0, uint32_t b1) {
    asm volatile("mma.sync.aligned.m16n8k16.row.col.f32.bf16.bf16.f32 "
                 "{%0,%1,%2,%3}, {%4,%5,%6,%7}, {%8,%9}, {%0,%1,%2,%3};"
                 : "+f"(c[0]), "+f"(c[1]), "+f"(c[2]), "+f"(c[3])
                 : "r"(a[0]), "r"(a[1]), "r"(a[2]), "r"(a[3]), "r"(b0), "r"(b1));
}
__device__ __forceinline__ float4 bn_relu4(float4 v, float4 a, float4 b) {
    v.x = fmaxf(fmaf(v.x, a.x, b.x), 0.f);
    v.y = fmaxf(fmaf(v.y, a.y, b.y), 0.f);
    v.z = fmaxf(fmaf(v.z, a.z, b.z), 0.f);
    v.w = fmaxf(fmaf(v.w, a.w, b.w), 0.f);
    return v;
}

// ---------------- init: zero counts/out/cnt + offsets ------------------------
__global__ void init_kernel(const int* __restrict__ nsub, float* __restrict__ out) {
    int i = blockIdx.x * blockDim.x + threadIdx.x;
    if (i < N_NODES) g_counts[i] = 0;
    float4 z = {0.f, 0.f, 0.f, 0.f};
    if (i < TOTAL_SUB * (D / 4)) ((float4*)out)[i] = z;
    if (i < TOTAL_SUB / 4) ((float4*)g_cnt)[i] = z;
    if (blockIdx.x == gridDim.x - 1 && threadIdx.x == 0) {
        int acc = 0;
        for (int g = 0; g < N_GRAPHS; g++) { g_off[g] = acc; acc += nsub[g]; }
    }
}

// ---------------- CSR build ---------------------------------------------------
__global__ void count_kernel(const int* __restrict__ dst) {
    int e = blockIdx.x * blockDim.x + threadIdx.x;
    if (e < N_EDGES) atomicAdd(&g_counts[dst[e]], 1);
}
__global__ void scan_kernel() {
    __shared__ int ssum[1024];
    int t = threadIdx.x;
    int base = t * 49;
    int s = 0;
    #pragma unroll 7
    for (int i = 0; i < 49; i++) {
        int idx = base + i;
        if (idx < N_NODES) s += g_counts[idx];
    }
    ssum[t] = s;
    __syncthreads();
    for (int off = 1; off < 1024; off <<= 1) {
        int v = (t >= off) ? ssum[t - off] : 0;
        __syncthreads();
        ssum[t] += v;
        __syncthreads();
    }
    int run = ssum[t] - s;
    for (int i = 0; i < 49; i++) {
        int idx = base + i;
        if (idx < N_NODES) {
            g_rowptr[idx] = run;
            g_cursor[idx] = run;
            run += g_counts[idx];
        }
    }
}
__global__ void fill_kernel(const int* __restrict__ src,
                            const int* __restrict__ dst,
                            const float* __restrict__ ea) {
    int e = blockIdx.x * blockDim.x + threadIdx.x;
    if (e >= N_EDGES) return;
    int d = dst[e];
    int slot = atomicAdd(&g_cursor[d], 1);
    g_edges[slot] = make_float2(__int_as_float(src[e]), ea[e]);
}

// ---------------- gather: agg[i] = sum_{j->i} w*h[j] (fp32, 1 warp/node) -----
__global__ void gather_kernel(const float* __restrict__ h) {
    if (blockIdx.x == 0 && threadIdx.x < (2 * D) / 4)
        ((float4*)g_stats)[threadIdx.x] = make_float4(0.f, 0.f, 0.f, 0.f);
    int t = blockIdx.x * blockDim.x + threadIdx.x;
    int node = t >> 5, lane = t & 31;
    if (node >= N_NODES) return;
    int beg = g_rowptr[node];
    int cnt = g_counts[node];
    float4 acc = {0.f, 0.f, 0.f, 0.f};
    int j = 0;
    for (; j + 8 <= cnt; j += 8) {
        float2 e[8];
        #pragma unroll
        for (int u = 0; u < 8; u++) e[u] = g_edges[beg + j + u];
        float4 v[8];
        #pragma unroll
        for (int u = 0; u < 8; u++)
            v[u] = ((const float4*)(h + (size_t)__float_as_int(e[u].x) * D))[lane];
        #pragma unroll
        for (int u = 0; u < 8; u++) {
            acc.x += e[u].y * v[u].x; acc.y += e[u].y * v[u].y;
            acc.z += e[u].y * v[u].z; acc.w += e[u].y * v[u].w;
        }
    }
    for (; j + 4 <= cnt; j += 4) {
        float2 e[4];
        #pragma unroll
        for (int u = 0; u < 4; u++) e[u] = g_edges[beg + j + u];
        float4 v[4];
        #pragma unroll
        for (int u = 0; u < 4; u++)
            v[u] = ((const float4*)(h + (size_t)__float_as_int(e[u].x) * D))[lane];
        #pragma unroll
        for (int u = 0; u < 4; u++) {
            acc.x += e[u].y * v[u].x; acc.y += e[u].y * v[u].y;
            acc.z += e[u].y * v[u].z; acc.w += e[u].y * v[u].w;
        }
    }
    for (; j < cnt; j++) {
        float2 e0 = g_edges[beg + j];
        float4 v0 = ((const float4*)(h + (size_t)__float_as_int(e0.x) * D))[lane];
        acc.x += e0.y * v0.x; acc.y += e0.y * v0.y;
        acc.z += e0.y * v0.z; acc.w += e0.y * v0.w;
    }
    ((float4*)(g_agg + (size_t)node * D))[lane] = acc;
}

// W[l][k][n] -> padded [n][k] bf16 hi/lo images
__global__ void prep_B_kernel(const float* __restrict__ Wrel,
                              const float* __restrict__ Wroot) {
    int idx = blockIdx.x * blockDim.x + threadIdx.x;
    if (idx >= NLAYERS * 2 * D * D) return;
    int l   = idx / (2 * D * D);
    int rem = idx % (2 * D * D);
    int mat = rem / (D * D);
    int e   = rem % (D * D);
    int n = e & 127, k = e >> 7;
    const float* W = (mat == 0) ? Wrel : Wroot;
    float x = W[(size_t)l * D * D + k * D + n];
    __nv_bfloat16 hi = __float2bfloat16_rn(x);
    float r = x - __bfloat162float(hi);
    __nv_bfloat16 lo = __float2bfloat16_rn(r);
    uint32_t off = (uint32_t)(n * IMG_STRIDE_B + k * 2);
    unsigned char* base = g_Bimg + (size_t)l * (4 * IMG_BYTES) + mat * (2 * IMG_BYTES);
    *(__nv_bfloat16*)(base + off)             = hi;
    *(__nv_bfloat16*)(base + IMG_BYTES + off) = lo;
}

// ---------------- mma.sync GEMM (R4 plain epilogue) ---------------------------
#define SM_A_HI   0
#define SM_A_LO   IMG_BYTES
#define SM_B      (2 * IMG_BYTES)
#define SM_BIAS   (6 * IMG_BYTES)
#define SM_TOTAL  (6 * IMG_BYTES + 512)

__device__ __forceinline__ void convert_rows(const float* __restrict__ src, int row0,
                                             char* sa_hi, char* sa_lo, int t) {
    int row = t >> 1, kh = (t & 1) * 64;
    bool valid = (row0 + row) < N_NODES;
    const float4* sr = (const float4*)(src + (size_t)(row0 + row) * D + kh);
    uint32_t base = (uint32_t)(row * IMG_STRIDE_B + kh * 2);
    #pragma unroll
    for (int i = 0; i < 8; i++) {
        float4 v0, v1;
        if (valid) { v0 = sr[2 * i]; v1 = sr[2 * i + 1]; }
        else       { v0 = make_float4(0.f, 0.f, 0.f, 0.f); v1 = v0; }
        float xs[8] = {v0.x, v0.y, v0.z, v0.w, v1.x, v1.y, v1.z, v1.w};
        uint32_t hp[4], lp[4];
        #pragma unroll
        for (int j = 0; j < 4; j++) {
            __nv_bfloat162 hpair = __floats2bfloat162_rn(xs[2 * j], xs[2 * j + 1]);
            float r0 = xs[2 * j]     - __low2float(hpair);
            float r1 = xs[2 * j + 1] - __high2float(hpair);
            __nv_bfloat162 lpair = __floats2bfloat162_rn(r0, r1);
            hp[j] = *(uint32_t*)&hpair;
            lp[j] = *(uint32_t*)&lpair;
        }
        *(uint4*)(sa_hi + base + i * 16) = make_uint4(hp[0], hp[1], hp[2], hp[3]);
        *(uint4*)(sa_lo + base + i * 16) = make_uint4(lp[0], lp[1], lp[2], lp[3]);
    }
}

__global__ __launch_bounds__(256, 1)
void gemm_kernel(const float* __restrict__ h,
                 const float* __restrict__ brel,
                 const float* __restrict__ broot,
                 int layer) {
    extern __shared__ char sm[];
    uint32_t smb = smem_to_u32(sm);
    const int tid = threadIdx.x;
    const int wid = tid >> 5, lane = tid & 31;
    const int wm = wid & 3, wn = wid >> 2;
    const int q = lane >> 3, lr = lane & 7;
    const int gid = lane >> 2, tg = lane & 3;

    {
        const uint4* gB = (const uint4*)(g_Bimg + (size_t)layer * (4 * IMG_BYTES));
        uint4* sB = (uint4*)(sm + SM_B);
        #pragma unroll 4
        for (int i = tid; i < (4 * IMG_BYTES) / 16; i += 256) sB[i] = gB[i];
    }
    if (tid < D) ((float*)(sm + SM_BIAS))[tid] = brel[tid] + broot[tid];
    __syncthreads();

    const uint32_t abase = (uint32_t)((wm * 32 + (q & 1) * 8 + lr) * IMG_STRIDE_B + (q >> 1) * 16);
    const uint32_t bbase = (uint32_t)((wn * 64 + (q >> 1) * 8 + lr) * IMG_STRIDE_B + (q & 1) * 16);
    const float* sbias = (const float*)(sm + SM_BIAS);

    for (int tile = blockIdx.x; tile < NTILES; tile += gridDim.x) {
        const int row0 = tile * 128;
        float acc[2][8][4];
        #pragma unroll
        for (int mt = 0; mt < 2; mt++)
            #pragma unroll
            for (int nt = 0; nt < 8; nt++)
                #pragma unroll
                for (int r = 0; r < 4; r++) acc[mt][nt][r] = 0.f;

        #pragma unroll
        for (int chunk = 0; chunk < 2; chunk++) {
            const float* src = (chunk == 0) ? g_agg : h;
            convert_rows(src, row0, sm + SM_A_HI, sm + SM_A_LO, tid);
            __syncthreads();

            const uint32_t aH = smb + SM_A_HI + abase;
            const uint32_t aL = smb + SM_A_LO + abase;
            const uint32_t bB = smb + SM_B + chunk * (2 * IMG_BYTES) + bbase;

            #pragma unroll
            for (int ks = 0; ks < 8; ks++) {
                uint32_t ah0[4], ah1[4], al0[4], al1[4];
                ldsm4(ah0, aH + ks * 32);
                ldsm4(ah1, aH + 16 * IMG_STRIDE_B + ks * 32);
                ldsm4(al0, aL + ks * 32);
                ldsm4(al1, aL + 16 * IMG_STRIDE_B + ks * 32);
                uint32_t bh[4][4], bl[4][4];
                #pragma unroll
                for (int nt2 = 0; nt2 < 4; nt2++) {
                    ldsm4(bh[nt2], bB + nt2 * 16 * IMG_STRIDE_B + ks * 32);
                    ldsm4(bl[nt2], bB + IMG_BYTES + nt2 * 16 * IMG_STRIDE_B + ks * 32);
                }
                #pragma unroll
                for (int nt = 0; nt < 8; nt++) {
                    uint32_t b0h = bh[nt >> 1][(nt & 1) * 2];
                    uint32_t b1h = bh[nt >> 1][(nt & 1) * 2 + 1];
                    uint32_t b0l = bl[nt >> 1][(nt & 1) * 2];
                    uint32_t b1l = bl[nt >> 1][(nt & 1) * 2 + 1];
                    mma16816(acc[0][nt], ah0, b0h, b1h);
                    mma16816(acc[1][nt], ah1, b0h, b1h);
                    mma16816(acc[0][nt], al0, b0h, b1h);
                    mma16816(acc[1][nt], al1, b0h, b1h);
                    mma16816(acc[0][nt], ah0, b0l, b1l);
                    mma16816(acc[1][nt], ah1, b0l, b1l);
                }
            }
            __syncthreads();
        }

        #pragma unroll
        for (int mt = 0; mt < 2; mt++) {
            int r0 = row0 + wm * 32 + mt * 16 + gid;
            #pragma unroll
            for (int nt = 0; nt < 8; nt++) {
                int c = wn * 64 + nt * 8 + tg * 2;
                float bx = sbias[c], by = sbias[c + 1];
                if (r0 < N_NODES) {
                    float2 o = {acc[mt][nt][0] + bx, acc[mt][nt][1] + by};
                    *(float2*)(g_hnew + (size_t)r0 * D + c) = o;
                }
                if (r0 + 8 < N_NODES) {
                    float2 o = {acc[mt][nt][2] + bx, acc[mt][nt][3] + by};
                    *(float2*)(g_hnew + (size_t)(r0 + 8) * D + c) = o;
                }
            }
        }
        __syncthreads();
    }
}

// ---------------- BN stats over hnew -----------------------------------------
__global__ void stats_kernel() {
    __shared__ float red[256 * 8];
    int t = threadIdx.x;
    float4 ps = {0.f,0.f,0.f,0.f}, pq = {0.f,0.f,0.f,0.f};
    const float4* src = (const float4*)g_hnew;
    for (int i = blockIdx.x * blockDim.x + t; i < N_NODES * (D / 4);
         i += gridDim.x * blockDim.x) {
        float4 v = src[i];
        ps.x += v.x; ps.y += v.y; ps.z += v.z; ps.w += v.w;
        pq.x += v.x*v.x; pq.y += v.y*v.y; pq.z += v.z*v.z; pq.w += v.w*v.w;
    }
    red[t*8+0]=ps.x; red[t*8+1]=ps.y; red[t*8+2]=ps.z; red[t*8+3]=ps.w;
    red[t*8+4]=pq.x; red[t*8+5]=pq.y; red[t*8+6]=pq.z; red[t*8+7]=pq.w;
    __syncthreads();
    if (t < D) {
        float s = 0.f, q = 0.f;
        #pragma unroll
        for (int g2 = 0; g2 < 8; g2++) {
            int st = g2 * 32 + (t >> 2);
            s += red[st * 8 + (t & 3)];
            q += red[st * 8 + 4 + (t & 3)];
        }
        atomicAdd(g_stats + t, s);
        atomicAdd(g_stats + D + t, q);
    }
}

// ---------------- fused BN-finalize + normalize + relu (layers 0..3) ----------
__global__ void norm_relu_kernel(const float* __restrict__ gamma,
                                 const float* __restrict__ beta) {
    __shared__ float sA[D], sB[D];
    int t = threadIdx.x;
    if (t < D) {
        float mu  = g_stats[t] * (1.0f / N_NODES);
        float var = g_stats[D + t] * (1.0f / N_NODES) - mu * mu;
        float inv = rsqrtf(var + BN_EPS);
        float a   = gamma[t] * inv;
        sA[t] = a;
        sB[t] = beta[t] - mu * a;
    }
    __syncthreads();
    int i = blockIdx.x * blockDim.x + t;
    if (i >= N_NODES * (D / 4)) return;
    int cg = i & 31;
    float4 a = ((const float4*)sA)[cg];
    float4 b = ((const float4*)sB)[cg];
    float4 v = ((const float4*)g_hnew)[i];
    ((float4*)g_h)[i] = bn_relu4(v, a, b);
}

// last layer: just compute coefficients; pool applies them
__global__ void bn_finalize_kernel(const float* __restrict__ gamma,
                                   const float* __restrict__ beta) {
    int c = threadIdx.x;
    float mu  = g_stats[c] * (1.0f / N_NODES);
    float var = g_stats[D + c] * (1.0f / N_NODES) - mu * mu;
    float inv = rsqrtf(var + BN_EPS);
    float a   = gamma[c] * inv;
    g_bnA[c] = a;
    g_bnB[c] = beta[c] - mu * a;
}

// ---------------- pooling ----------------------------------------------------
// pool reads final hnew (pre-BN), applies last layer's BN+relu on the fly
__global__ void pool_kernel(const int* __restrict__ batch,
                            const int* __restrict__ subb,
                            float* __restrict__ out) {
    int t = blockIdx.x * blockDim.x + threadIdx.x;
    int node = t >> 5, lane = t & 31;
    if (node >= N_NODES) return;
    float4 a4 = ((const float4*)g_bnA)[lane];
    float4 b4 = ((const float4*)g_bnB)[lane];
    int sid = g_off[batch[node]] + subb[node];
    float4 v = ((const float4*)(g_hnew + (size_t)node * D))[lane];
    v = bn_relu4(v, a4, b4);
    red_add_v4(out + (size_t)sid * D + lane * 4, v);
    if (lane == 0) atomicAdd(g_cnt + sid, 1.f);
}
__global__ void div_kernel(float* __restrict__ out) {
    int i = blockIdx.x * blockDim.x + threadIdx.x;
    if (i >= TOTAL_SUB * (D / 4)) return;
    float inv = 1.0f / fmaxf(g_cnt[i >> 5], 1.0f);
    float4 v = ((float4*)out)[i];
    v.x *= inv; v.y *= inv; v.z *= inv; v.w *= inv;
    ((float4*)out)[i] = v;
}

// ---------------- launch ------------------------------------------------------
extern "C" void kernel_launch(void* const* d_in, const int* in_sizes, int n_in,
                              void* d_out, int out_size) {
    const float* x     = (const float*)d_in[0];
    const float* ea    = (const float*)d_in[1];
    const float* Wrel  = (const float*)d_in[2];
    const float* brel  = (const float*)d_in[3];
    const float* Wroot = (const float*)d_in[4];
    const float* broot = (const float*)d_in[5];
    const float* gamma = (const float*)d_in[6];
    const float* beta  = (const float*)d_in[7];
    const int*   ei    = (const int*)d_in[8];
    const int*   batch = (const int*)d_in[9];
    const int*   nsub  = (const int*)d_in[10];
    const int*   subb  = (const int*)d_in[11];
    float*       out   = (float*)d_out;

    cudaFuncSetAttribute(gemm_kernel,
                         cudaFuncAttributeMaxDynamicSharedMemorySize, SM_TOTAL);

    void* p = nullptr;
    cudaGetSymbolAddress(&p, g_h);
    const float* gh = (const float*)p;

    const int* src = ei;
    const int* dst = ei + N_EDGES;

    init_kernel<<<(TOTAL_SUB * (D / 4) + 255) / 256, 256>>>(nsub, out);       // 1
    count_kernel<<<(N_EDGES + 255) / 256, 256>>>(dst);                        // 2
    scan_kernel<<<1, 1024>>>();                                               // 3
    fill_kernel<<<(N_EDGES + 255) / 256, 256>>>(src, dst, ea);                // 4

    const float* hcur = x;
    for (int l = 0; l < NLAYERS; l++) {
        gather_kernel<<<(N_NODES * 32 + 255) / 256, 256>>>(hcur);
        if (l == 0)
            prep_B_kernel<<<(NLAYERS * 2 * D * D + 255) / 256, 256>>>(Wrel, Wroot);
        gemm_kernel<<<148, 256, SM_TOTAL>>>(hcur,
                                            brel + (size_t)l * D,
                                            broot + (size_t)l * D, l);
        stats_kernel<<<592, 256>>>();
        if (l < NLAYERS - 1) {
            norm_relu_kernel<<<(N_NODES * (D / 4) + 255) / 256, 256>>>(
                gamma + (size_t)l * D, beta + (size_t)l * D);
            hcur = gh;
        } else {
            bn_finalize_kernel<<<1, D>>>(gamma + (size_t)l * D,
                                         beta + (size_t)l * D);
        }
    }
    pool_kernel<<<(N_NODES * 32 + 255) / 256, 256>>>(batch, subb, out);
    div_kernel<<<(TOTAL_SUB * (D / 4) + 255) / 256, 256>>>(out);
}